// round 4
// baseline (speedup 1.0000x reference)
#include <cuda_runtime.h>

#define N_NODES 20000
#define N_EDGES 320000
#define D 256

// ---------------- scratch (no allocations allowed) ----------------
__device__ float g_aggr[N_NODES * D];        // segment-mean result
__device__ int   g_count[N_NODES];
__device__ int   g_off[N_NODES + 1];
__device__ int   g_cursor[N_NODES];
__device__ int   g_srclist[N_EDGES];
__device__ int   g_is64;

// ---------------- dtype sniff: int64 vs int32 edge_index ----------------
// int64 little-endian with values in [0, 20000): every odd 32-bit word is 0.
// For int32 data those words are random edge indices; P(512 all zero) ~ 0.
__global__ void detect_kernel(const int* __restrict__ ei) {
    if (threadIdx.x == 0) {
        int flag = 1;
        for (int i = 0; i < 512; i++) {
            if (ei[2 * i + 1] != 0) { flag = 0; break; }
        }
        g_is64 = flag;
    }
}

__global__ void zero_kernel() {
    int i = blockIdx.x * blockDim.x + threadIdx.x;
    if (i < N_NODES) { g_count[i] = 0; g_cursor[i] = 0; }
}

__global__ void count_kernel(const int* __restrict__ ei) {
    int e = blockIdx.x * blockDim.x + threadIdx.x;
    if (e >= N_EDGES) return;
    int dst = g_is64 ? ei[2 * (N_EDGES + e)] : ei[N_EDGES + e];
    atomicAdd(&g_count[dst], 1);
}

// single-block exclusive scan over 20000 counts (1024 thr x 20 elems)
__global__ void scan_kernel() {
    __shared__ int s[1024];
    const int C = 20;                       // 1024*20 = 20480 >= 20000
    int tid = threadIdx.x;
    int base = tid * C;
    int lc[C];
    int local = 0;
#pragma unroll
    for (int i = 0; i < C; i++) {
        int idx = base + i;
        lc[i] = (idx < N_NODES) ? g_count[idx] : 0;
        local += lc[i];
    }
    s[tid] = local;
    __syncthreads();
    for (int off = 1; off < 1024; off <<= 1) {
        int v = (tid >= off) ? s[tid - off] : 0;
        __syncthreads();
        s[tid] += v;
        __syncthreads();
    }
    int running = s[tid] - local;           // exclusive prefix for this chunk
#pragma unroll
    for (int i = 0; i < C; i++) {
        int idx = base + i;
        if (idx < N_NODES) g_off[idx] = running;
        running += lc[i];
    }
    if (tid == 1023) g_off[N_NODES] = s[1023];
}

__global__ void fill_kernel(const int* __restrict__ ei) {
    int e = blockIdx.x * blockDim.x + threadIdx.x;
    if (e >= N_EDGES) return;
    int src, dst;
    if (g_is64) { src = ei[2 * e];          dst = ei[2 * (N_EDGES + e)]; }
    else        { src = ei[e];              dst = ei[N_EDGES + e]; }
    int pos = atomicAdd(&g_cursor[dst], 1);
    g_srclist[g_off[dst] + pos] = src;
}

// one block per node, one thread per feature column; src indices staged in
// smem so the x-row reads are coalesced 128B/warp and independent (high MLP).
#define AGG_TILE 64
__global__ void aggregate_kernel(const float* __restrict__ x) {
    int n = blockIdx.x;
    int c = threadIdx.x;                    // 256 threads = d columns
    __shared__ int ssrc[AGG_TILE];
    int off0 = g_off[n];
    int off1 = g_off[n + 1];
    float sum = 0.f;
    for (int base = off0; base < off1; base += AGG_TILE) {
        int cnt = min(AGG_TILE, off1 - base);
        __syncthreads();
        if (c < cnt) ssrc[c] = g_srclist[base + c];
        __syncthreads();
#pragma unroll 4
        for (int i = 0; i < cnt; i++)
            sum += __ldg(&x[(long)ssrc[i] * D + c]);
    }
    float inv = 1.0f / fmaxf((float)(off1 - off0), 1.0f);
    g_aggr[n * D + c] = sum * inv;
}

// ---------------- fused GEMM: out = aggr@Wl^T + x@Wr^T + br ----------------
// 128x128x16 tile, 256 threads, 8x8 per-thread tile as 32 f32x2 accumulators.
// A tile stored DUPLICATED ({a,a} pairs) so the broadcast operand of
// fma.rn.f32x2 is a plain b64 smem load — no packing MOVs in the inner loop.

__device__ __forceinline__ unsigned long long ffma2(
    unsigned long long a, unsigned long long b, unsigned long long c) {
    unsigned long long d;
    asm("fma.rn.f32x2 %0, %1, %2, %3;" : "=l"(d) : "l"(a), "l"(b), "l"(c));
    return d;
}

#define BM 128
#define BN 128
#define BK 16

__global__ __launch_bounds__(256, 2)
void gemm_kernel(const float* __restrict__ x,
                 const float* __restrict__ Wl,
                 const float* __restrict__ Wr,
                 const float* __restrict__ br,
                 float* __restrict__ out) {
    __shared__ __align__(16) float Asd[BK][2 * BM];   // 16 KB, duplicated pairs
    __shared__ __align__(16) float Bs[BK][BN];        // 8 KB

    int tid  = threadIdx.x;
    int tx   = tid & 15;                 // col group 0..15
    int ty   = tid >> 4;                 // row group 0..15
    int row0 = blockIdx.x * BM;
    int col0 = blockIdx.y * BN;
    int m0   = ty * 8;
    int n0   = tx * 8;

    unsigned long long acc[8][4];
#pragma unroll
    for (int r = 0; r < 8; r++)
#pragma unroll
        for (int c = 0; c < 4; c++) acc[r][c] = 0ULL;

    for (int phase = 0; phase < 2; phase++) {
        const float* A = phase ? x  : g_aggr;
        const float* W = phase ? Wr : Wl;
        for (int kt = 0; kt < D; kt += BK) {
            __syncthreads();
            // cooperative tile load: 512 float4 per matrix, 2 per thread
#pragma unroll
            for (int l = 0; l < 2; l++) {
                int j  = tid + l * 256;
                int r  = j >> 2;                 // 0..127
                int kc = (j & 3) << 2;           // 0,4,8,12
                int grow = row0 + r;
                float4 v = make_float4(0.f, 0.f, 0.f, 0.f);
                if (grow < N_NODES)
                    v = *reinterpret_cast<const float4*>(&A[grow * D + kt + kc]);
                Asd[kc + 0][2 * r] = v.x; Asd[kc + 0][2 * r + 1] = v.x;
                Asd[kc + 1][2 * r] = v.y; Asd[kc + 1][2 * r + 1] = v.y;
                Asd[kc + 2][2 * r] = v.z; Asd[kc + 2][2 * r + 1] = v.z;
                Asd[kc + 3][2 * r] = v.w; Asd[kc + 3][2 * r + 1] = v.w;
                float4 w = *reinterpret_cast<const float4*>(&W[(col0 + r) * D + kt + kc]);
                Bs[kc + 0][r] = w.x; Bs[kc + 1][r] = w.y;
                Bs[kc + 2][r] = w.z; Bs[kc + 3][r] = w.w;
            }
            __syncthreads();
#pragma unroll
            for (int k = 0; k < BK; k++) {
                ulonglong2 a0 = *reinterpret_cast<const ulonglong2*>(&Asd[k][2 * m0]);
                ulonglong2 a1 = *reinterpret_cast<const ulonglong2*>(&Asd[k][2 * m0 + 4]);
                ulonglong2 a2 = *reinterpret_cast<const ulonglong2*>(&Asd[k][2 * m0 + 8]);
                ulonglong2 a3 = *reinterpret_cast<const ulonglong2*>(&Asd[k][2 * m0 + 12]);
                ulonglong2 b0 = *reinterpret_cast<const ulonglong2*>(&Bs[k][n0]);
                ulonglong2 b1 = *reinterpret_cast<const ulonglong2*>(&Bs[k][n0 + 4]);
                unsigned long long av[8] = {a0.x, a0.y, a1.x, a1.y,
                                            a2.x, a2.y, a3.x, a3.y};
                unsigned long long bv[4] = {b0.x, b0.y, b1.x, b1.y};
#pragma unroll
                for (int r = 0; r < 8; r++)
#pragma unroll
                    for (int c = 0; c < 4; c++)
                        acc[r][c] = ffma2(av[r], bv[c], acc[r][c]);
            }
        }
    }

    // epilogue: unpack f32x2 pairs, add bias, store as float2
#pragma unroll
    for (int r = 0; r < 8; r++) {
        int grow = row0 + m0 + r;
        if (grow < N_NODES) {
#pragma unroll
            for (int c = 0; c < 4; c++) {
                int gcol = col0 + n0 + 2 * c;
                unsigned long long v = acc[r][c];
                float lo = __uint_as_float((unsigned int)(v & 0xffffffffULL)) + br[gcol];
                float hi = __uint_as_float((unsigned int)(v >> 32))           + br[gcol + 1];
                *reinterpret_cast<float2*>(&out[grow * D + gcol]) = make_float2(lo, hi);
            }
        }
    }
}

// ---------------- launch ----------------
extern "C" void kernel_launch(void* const* d_in, const int* in_sizes, int n_in,
                              void* d_out, int out_size) {
    const float* x  = (const float*)d_in[0];
    const int*   ei = (const int*)d_in[1];    // int32 view; int64 handled via g_is64
    const float* Wl = (const float*)d_in[2];
    const float* Wr = (const float*)d_in[3];
    const float* br = (const float*)d_in[4];
    float* out = (float*)d_out;

    detect_kernel<<<1, 32>>>(ei);
    zero_kernel<<<(N_NODES + 255) / 256, 256>>>();
    count_kernel<<<(N_EDGES + 255) / 256, 256>>>(ei);
    scan_kernel<<<1, 1024>>>();
    fill_kernel<<<(N_EDGES + 255) / 256, 256>>>(ei);
    aggregate_kernel<<<N_NODES, 256>>>(x);
    gemm_kernel<<<dim3((N_NODES + BM - 1) / BM, D / BN), 256>>>(x, Wl, Wr, br, out);
}

// round 7
// speedup vs baseline: 2.0853x; 2.0853x over previous
#include <cuda_runtime.h>
#include <cuda_bf16.h>
#include <cstdint>

#define N_NODES 20000
#define N_EDGES 320000
#define D 256

// ---------------- scratch (no allocations allowed) ----------------
// A' = [hi(aggr)|hi(x)|lo(aggr)|lo(x)] per row: 1024 bf16 cols
__device__ __nv_bfloat16 g_Ahl[(size_t)N_NODES * 1024];
// W' = [hi(Wl)|hi(Wr)|lo(Wl)|lo(Wr)] per output col: 1024 bf16 cols
__device__ __nv_bfloat16 g_Whl[256 * 1024];
__device__ int g_count[N_NODES];
__device__ int g_off[N_NODES + 1];
__device__ int g_cursor[N_NODES];
__device__ int g_srclist[N_EDGES];
__device__ int g_is64;

// ---------------- helpers ----------------
__device__ __forceinline__ uint32_t smem_u32(const void* p) {
    uint32_t a;
    asm("{ .reg .u64 t; cvta.to.shared.u64 t, %1; cvt.u32.u64 %0, t; }"
        : "=r"(a) : "l"(p));
    return a;
}
__device__ __forceinline__ void split_bf16(float v, __nv_bfloat16& hi, __nv_bfloat16& lo) {
    hi = __float2bfloat16(v);
    lo = __float2bfloat16(v - __bfloat162float(hi));
}
__device__ __forceinline__ void cp16(uint32_t dst, const void* src, int srcsz) {
    asm volatile("cp.async.cg.shared.global [%0], [%1], 16, %2;"
                 :: "r"(dst), "l"(src), "r"(srcsz));
}
__device__ __forceinline__ void cp_commit() { asm volatile("cp.async.commit_group;" ::: "memory"); }
__device__ __forceinline__ void cp_wait1()  { asm volatile("cp.async.wait_group 1;" ::: "memory"); }
__device__ __forceinline__ void cp_wait0()  { asm volatile("cp.async.wait_group 0;" ::: "memory"); }

__device__ __forceinline__ void ldm_x4(uint32_t* r, uint32_t addr) {
    asm volatile("ldmatrix.sync.aligned.m8n8.x4.shared.b16 {%0,%1,%2,%3}, [%4];"
                 : "=r"(r[0]), "=r"(r[1]), "=r"(r[2]), "=r"(r[3]) : "r"(addr));
}
__device__ __forceinline__ void mma16816(float* d, const uint32_t* a, const uint32_t* b) {
    asm volatile("mma.sync.aligned.m16n8k16.row.col.f32.bf16.bf16.f32 "
                 "{%0,%1,%2,%3}, {%4,%5,%6,%7}, {%8,%9}, {%0,%1,%2,%3};"
                 : "+f"(d[0]), "+f"(d[1]), "+f"(d[2]), "+f"(d[3])
                 : "r"(a[0]), "r"(a[1]), "r"(a[2]), "r"(a[3]), "r"(b[0]), "r"(b[1]));
}

// ---------------- dtype sniff: int64 vs int32 edge_index ----------------
__global__ void detect_kernel(const int* __restrict__ ei) {
    if (threadIdx.x == 0) {
        int flag = 1;
        for (int i = 0; i < 512; i++)
            if (ei[2 * i + 1] != 0) { flag = 0; break; }
        g_is64 = flag;
    }
}

__global__ void zero_kernel() {
    int i = blockIdx.x * blockDim.x + threadIdx.x;
    if (i < N_NODES) { g_count[i] = 0; g_cursor[i] = 0; }
}

__global__ void count_kernel(const int* __restrict__ ei) {
    int e = blockIdx.x * blockDim.x + threadIdx.x;
    if (e >= N_EDGES) return;
    int dst = g_is64 ? ei[2 * (N_EDGES + e)] : ei[N_EDGES + e];
    atomicAdd(&g_count[dst], 1);
}

// single-block exclusive scan; no local array (avoids the reg-spill that cost 16us)
__global__ void scan_kernel() {
    __shared__ int s[1024];
    const int C = 20;
    int tid = threadIdx.x;
    int base = tid * C;
    int local = 0;
#pragma unroll
    for (int i = 0; i < C; i++) {
        int idx = base + i;
        if (idx < N_NODES) local += g_count[idx];
    }
    s[tid] = local;
    __syncthreads();
    for (int off = 1; off < 1024; off <<= 1) {
        int v = (tid >= off) ? s[tid - off] : 0;
        __syncthreads();
        s[tid] += v;
        __syncthreads();
    }
    int running = s[tid] - local;
#pragma unroll
    for (int i = 0; i < C; i++) {
        int idx = base + i;
        if (idx < N_NODES) {
            g_off[idx] = running;
            running += g_count[idx];   // L2-hit reload, no spill
        }
    }
    if (tid == 1023) g_off[N_NODES] = s[1023];
}

__global__ void fill_kernel(const int* __restrict__ ei) {
    int e = blockIdx.x * blockDim.x + threadIdx.x;
    if (e >= N_EDGES) return;
    int src, dst;
    if (g_is64) { src = ei[2 * e]; dst = ei[2 * (N_EDGES + e)]; }
    else        { src = ei[e];     dst = ei[N_EDGES + e]; }
    int pos = atomicAdd(&g_cursor[dst], 1);
    g_srclist[g_off[dst] + pos] = src;
}

// x hi/lo conversion into A' cols [256:512) and [768:1024)
__global__ void conv_x_kernel(const float* __restrict__ x) {
    int n = blockIdx.x;
    int c = threadIdx.x;
    float v = x[n * D + c];
    __nv_bfloat16 hi, lo;
    split_bf16(v, hi, lo);
    g_Ahl[(size_t)n * 1024 + 256 + c] = hi;
    g_Ahl[(size_t)n * 1024 + 768 + c] = lo;
}

// W' build: rows = output cols
__global__ void conv_w_kernel(const float* __restrict__ Wl, const float* __restrict__ Wr) {
    int n = blockIdx.x;   // 0..255
    int c = threadIdx.x;  // 0..255
    __nv_bfloat16 hi, lo;
    split_bf16(Wl[n * D + c], hi, lo);
    g_Whl[n * 1024 + c] = hi;       g_Whl[n * 1024 + 512 + c] = lo;
    split_bf16(Wr[n * D + c], hi, lo);
    g_Whl[n * 1024 + 256 + c] = hi; g_Whl[n * 1024 + 768 + c] = lo;
}

// aggregation (segment-mean) fused with hi/lo conversion → A' cols [0:256),[512:768)
#define AGG_TILE 64
__global__ void aggregate_kernel(const float* __restrict__ x) {
    int n = blockIdx.x;
    int c = threadIdx.x;
    __shared__ int ssrc[AGG_TILE];
    int off0 = g_off[n];
    int off1 = g_off[n + 1];
    float sum = 0.f;
    for (int base = off0; base < off1; base += AGG_TILE) {
        int cnt = min(AGG_TILE, off1 - base);
        __syncthreads();
        if (c < cnt) ssrc[c] = g_srclist[base + c];
        __syncthreads();
#pragma unroll 4
        for (int i = 0; i < cnt; i++)
            sum += __ldg(&x[(size_t)ssrc[i] * D + c]);
    }
    float m = sum * (1.0f / fmaxf((float)(off1 - off0), 1.0f));
    __nv_bfloat16 hi, lo;
    split_bf16(m, hi, lo);
    g_Ahl[(size_t)n * 1024 + c] = hi;
    g_Ahl[(size_t)n * 1024 + 512 + c] = lo;
}

// ---------------- mma.sync bf16 GEMM ----------------
// out[20000,256] = A'[20000,1536_eff] @ W'^T + bias, via 24 K-chunks of 64.
// CTA tile 128x128, 8 warps (2M x 4N), warp tile 64x32, m16n8k16 HMMA.
// Smem tiles [128 rows][64 bf16] with 16B-chunk XOR swizzle (chunk ^ (row&7)).
#define GT 256
#define CHUNKS 24
// smem: bias[256] f32 (1KB) + 2 buffers x (A 16KB + B 16KB)
#define SM_BIAS   0
#define SM_TILES  1024
#define SM_A(b)   (SM_TILES + (b) * 32768)
#define SM_B(b)   (SM_TILES + (b) * 32768 + 16384)
#define GEMM_SMEM (SM_TILES + 65536)

extern __shared__ char sm_dyn[];

__device__ __forceinline__ void stage_chunk(uint32_t sb, int b, int c, int row0, int col0,
                                            int tid) {
    int p  = c >> 3;
    int kc = (c & 7) * 64;
    int Acol = (p == 2) ? 512 : 0;
    int Wcol = (p == 1) ? 512 : 0;
    uint32_t smA = sb + SM_A(b), smB = sb + SM_B(b);
    const char* Abase = (const char*)g_Ahl;
    const char* Bbase = (const char*)g_Whl;
#pragma unroll
    for (int it = 0; it < 4; it++) {
        int u = it * GT + tid;              // 0..1023
        int r  = u >> 3;                    // row 0..127
        int ck = u & 7;                     // 16B chunk 0..7
        uint32_t swo = (uint32_t)(r * 8 + (ck ^ (r & 7))) * 16;
        int grow = row0 + r;
        int ok = (grow < N_NODES);
        const char* asrc = Abase + ((size_t)(ok ? grow : 0) * 1024 + Acol + kc + ck * 8) * 2;
        cp16(smA + swo, asrc, ok ? 16 : 0);
        const char* bsrc = Bbase + ((size_t)(col0 + r) * 1024 + Wcol + kc + ck * 8) * 2;
        cp16(smB + swo, bsrc, 16);
    }
    cp_commit();
}

__global__ void __launch_bounds__(GT, 2)
gemm_mma_kernel(const float* __restrict__ br, float* __restrict__ out) {
    uint32_t sb = smem_u32(sm_dyn);
    int tid  = threadIdx.x;
    int wid  = tid >> 5;
    int lane = tid & 31;
    int row0 = blockIdx.x * 128;
    int col0 = blockIdx.y * 128;
    int m0w  = (wid & 1) * 64;          // warp M origin in tile
    int n0w  = (wid >> 1) * 32;         // warp N origin in tile

    float* sBias = (float*)(sm_dyn + SM_BIAS);
    if (tid < 256) sBias[tid] = br[tid];

    float acc[4][4][4];
#pragma unroll
    for (int mt = 0; mt < 4; mt++)
#pragma unroll
        for (int nt = 0; nt < 4; nt++)
#pragma unroll
            for (int j = 0; j < 4; j++) acc[mt][nt][j] = 0.f;

    // per-lane ldmatrix address components
    int a_m  = m0w + (lane & 15);            // A row for this lane (per m-tile +16*mt)
    int a_kh = (lane >> 4);                  // 0/1 -> +8 k
    int b_n  = n0w + (lane & 7) + ((lane >> 4) & 1) * 8;  // per n-pair +16*np
    int b_kh = (lane >> 3) & 1;              // 0/1 -> +8 k

    stage_chunk(sb, 0, 0, row0, col0, tid);

    for (int c = 0; c < CHUNKS; c++) {
        int b = c & 1;
        if (c + 1 < CHUNKS) {
            stage_chunk(sb, b ^ 1, c + 1, row0, col0, tid);
            cp_wait1();
        } else {
            cp_wait0();
        }
        __syncthreads();

        uint32_t smA = sb + SM_A(b), smB = sb + SM_B(b);
#pragma unroll
        for (int ks = 0; ks < 4; ks++) {
            uint32_t afrag[4][4], bfrag[4][4];
            int ka = ks * 2 + a_kh;          // A 16B chunk index
            int kb = ks * 2 + b_kh;          // B 16B chunk index
#pragma unroll
            for (int mt = 0; mt < 4; mt++) {
                int m = a_m + mt * 16;
                ldm_x4(afrag[mt], smA + (uint32_t)(m * 8 + (ka ^ (m & 7))) * 16);
            }
#pragma unroll
            for (int np = 0; np < 2; np++) {
                int n = b_n + np * 16;
                uint32_t r4[4];
                ldm_x4(r4, smB + (uint32_t)(n * 8 + (kb ^ (n & 7))) * 16);
                bfrag[np * 2][0]     = r4[0]; bfrag[np * 2][1]     = r4[1];
                bfrag[np * 2 + 1][0] = r4[2]; bfrag[np * 2 + 1][1] = r4[3];
            }
#pragma unroll
            for (int mt = 0; mt < 4; mt++)
#pragma unroll
                for (int nt = 0; nt < 4; nt++)
                    mma16816(acc[mt][nt], afrag[mt], bfrag[nt]);
        }
        __syncthreads();
    }

    // epilogue: C fragment rows t/4 (+8), cols 2*(t%4); add bias, float2 stores
    int cr = lane >> 2;
    int cc = (lane & 3) * 2;
#pragma unroll
    for (int mt = 0; mt < 4; mt++) {
        int r0g = row0 + m0w + mt * 16 + cr;
#pragma unroll
        for (int nt = 0; nt < 4; nt++) {
            int colg = col0 + n0w + nt * 8 + cc;
            float b0 = sBias[colg], b1 = sBias[colg + 1];
            if (r0g < N_NODES)
                *reinterpret_cast<float2*>(&out[(size_t)r0g * 256 + colg]) =
                    make_float2(acc[mt][nt][0] + b0, acc[mt][nt][1] + b1);
            if (r0g + 8 < N_NODES)
                *reinterpret_cast<float2*>(&out[(size_t)(r0g + 8) * 256 + colg]) =
                    make_float2(acc[mt][nt][2] + b0, acc[mt][nt][3] + b1);
        }
    }
}

// ---------------- launch ----------------
extern "C" void kernel_launch(void* const* d_in, const int* in_sizes, int n_in,
                              void* d_out, int out_size) {
    const float* x  = (const float*)d_in[0];
    const int*   ei = (const int*)d_in[1];
    const float* Wl = (const float*)d_in[2];
    const float* Wr = (const float*)d_in[3];
    const float* br = (const float*)d_in[4];
    float* out = (float*)d_out;

    cudaFuncSetAttribute(gemm_mma_kernel,
                         cudaFuncAttributeMaxDynamicSharedMemorySize, GEMM_SMEM);

    detect_kernel<<<1, 32>>>(ei);
    zero_kernel<<<(N_NODES + 255) / 256, 256>>>();
    count_kernel<<<(N_EDGES + 255) / 256, 256>>>(ei);
    scan_kernel<<<1, 1024>>>();
    fill_kernel<<<(N_EDGES + 255) / 256, 256>>>(ei);
    conv_x_kernel<<<N_NODES, 256>>>(x);
    conv_w_kernel<<<256, 256>>>(Wl, Wr);
    aggregate_kernel<<<N_NODES, 256>>>(x);
    gemm_mma_kernel<<<dim3((N_NODES + 127) / 128, 2), GT, GEMM_SMEM>>>(br, out);
}

// round 8
// speedup vs baseline: 2.3957x; 1.1489x over previous
#include <cuda_runtime.h>
#include <cuda_bf16.h>
#include <cstdint>

#define N_NODES 20000
#define N_EDGES 320000
#define D 256
#define NB 79          // ceil(20000/256) scan blocks

// ---------------- scratch (no allocations allowed) ----------------
// A' = [hi(aggr)|hi(x)|lo(aggr)|lo(x)] per row: 1024 bf16 cols
__device__ __nv_bfloat16 g_Ahl[(size_t)N_NODES * 1024];
// W' = [hi(Wl)|hi(Wr)|lo(Wl)|lo(Wr)] per output col: 1024 bf16 cols
__device__ __nv_bfloat16 g_Whl[256 * 1024];
__device__ int g_count[N_NODES];
__device__ int g_off[N_NODES + 1];
__device__ int g_cursor[N_NODES];
__device__ int g_srclist[N_EDGES];
__device__ int g_bsum[NB];
__device__ int g_is64;

// ---------------- helpers ----------------
__device__ __forceinline__ uint32_t smem_u32(const void* p) {
    uint32_t a;
    asm("{ .reg .u64 t; cvta.to.shared.u64 t, %1; cvt.u32.u64 %0, t; }"
        : "=r"(a) : "l"(p));
    return a;
}
__device__ __forceinline__ void split_bf16(float v, __nv_bfloat16& hi, __nv_bfloat16& lo) {
    hi = __float2bfloat16(v);
    lo = __float2bfloat16(v - __bfloat162float(hi));
}
__device__ __forceinline__ void cp16(uint32_t dst, const void* src, int srcsz) {
    asm volatile("cp.async.cg.shared.global [%0], [%1], 16, %2;"
                 :: "r"(dst), "l"(src), "r"(srcsz));
}
__device__ __forceinline__ void cp_commit() { asm volatile("cp.async.commit_group;" ::: "memory"); }
__device__ __forceinline__ void cp_wait1()  { asm volatile("cp.async.wait_group 1;" ::: "memory"); }
__device__ __forceinline__ void cp_wait0()  { asm volatile("cp.async.wait_group 0;" ::: "memory"); }

__device__ __forceinline__ void ldm_x4(uint32_t* r, uint32_t addr) {
    asm volatile("ldmatrix.sync.aligned.m8n8.x4.shared.b16 {%0,%1,%2,%3}, [%4];"
                 : "=r"(r[0]), "=r"(r[1]), "=r"(r[2]), "=r"(r[3]) : "r"(addr));
}
__device__ __forceinline__ void mma16816(float* d, const uint32_t* a, const uint32_t* b) {
    asm volatile("mma.sync.aligned.m16n8k16.row.col.f32.bf16.bf16.f32 "
                 "{%0,%1,%2,%3}, {%4,%5,%6,%7}, {%8,%9}, {%0,%1,%2,%3};"
                 : "+f"(d[0]), "+f"(d[1]), "+f"(d[2]), "+f"(d[3])
                 : "r"(a[0]), "r"(a[1]), "r"(a[2]), "r"(a[3]), "r"(b[0]), "r"(b[1]));
}

// ---------------- init: zero counts + warp-parallel dtype sniff ----------------
// int64 little-endian with values < 2^31: every odd 32-bit word is 0.
__global__ void init_kernel(const int* __restrict__ ei) {
    int idx = blockIdx.x * 256 + threadIdx.x;
    if (idx < N_NODES) { g_count[idx] = 0; g_cursor[idx] = 0; }
    if (idx == 0) g_off[N_NODES] = N_EDGES;     // total edges, always
    if (blockIdx.x == 0 && threadIdx.x < 32) {
        int nz = 0;
        for (int i = threadIdx.x; i < 512; i += 32)
            nz |= (ei[2 * i + 1] != 0);
        unsigned m = __ballot_sync(0xffffffffu, nz);
        if (threadIdx.x == 0) g_is64 = (m == 0);
    }
}

// ---------------- count histogram + fused W hi/lo conversion ----------------
__global__ void count_kernel(const int* __restrict__ ei,
                             const float* __restrict__ Wl,
                             const float* __restrict__ Wr) {
    int e = blockIdx.x * blockDim.x + threadIdx.x;
    if (e < N_EDGES) {
        int dst = g_is64 ? ei[2 * (N_EDGES + e)] : ei[N_EDGES + e];
        atomicAdd(&g_count[dst], 1);
    }
    if (blockIdx.x < 256) {                      // fused conv_w: row = blockIdx
        int n = blockIdx.x, c = threadIdx.x;
        __nv_bfloat16 hi, lo;
        split_bf16(Wl[n * D + c], hi, lo);
        g_Whl[n * 1024 + c] = hi;       g_Whl[n * 1024 + 512 + c] = lo;
        split_bf16(Wr[n * D + c], hi, lo);
        g_Whl[n * 1024 + 256 + c] = hi; g_Whl[n * 1024 + 768 + c] = lo;
    }
}

// ---------------- hierarchical scan: per-block sums, then scan+write ----------------
__global__ void partsum_kernel() {
    __shared__ int s[256];
    int tid = threadIdx.x;
    int idx = blockIdx.x * 256 + tid;
    s[tid] = (idx < N_NODES) ? g_count[idx] : 0;
    __syncthreads();
    for (int o = 128; o > 0; o >>= 1) {
        if (tid < o) s[tid] += s[tid + o];
        __syncthreads();
    }
    if (tid == 0) g_bsum[blockIdx.x] = s[0];
}

__global__ void scanwrite_kernel() {
    __shared__ int bs[128];
    __shared__ int sc[256];
    int tid = threadIdx.x;
    int b = blockIdx.x;
    if (tid < 128) bs[tid] = (tid < NB) ? g_bsum[tid] : 0;
    __syncthreads();
    for (int o = 1; o < 128; o <<= 1) {               // inclusive scan of block sums
        int v = (tid < 128 && tid >= o) ? bs[tid - o] : 0;
        __syncthreads();
        if (tid < 128) bs[tid] += v;
        __syncthreads();
    }
    int bp = (b == 0) ? 0 : bs[b - 1];                // exclusive block prefix
    int idx = b * 256 + tid;
    int cnt = (idx < N_NODES) ? g_count[idx] : 0;
    sc[tid] = cnt;
    __syncthreads();
    for (int o = 1; o < 256; o <<= 1) {               // inclusive in-block scan
        int v = (tid >= o) ? sc[tid - o] : 0;
        __syncthreads();
        sc[tid] += v;
        __syncthreads();
    }
    if (idx < N_NODES) g_off[idx] = bp + sc[tid] - cnt;
}

__global__ void fill_kernel(const int* __restrict__ ei) {
    int e = blockIdx.x * blockDim.x + threadIdx.x;
    if (e >= N_EDGES) return;
    int src, dst;
    if (g_is64) { src = ei[2 * e]; dst = ei[2 * (N_EDGES + e)]; }
    else        { src = ei[e];     dst = ei[N_EDGES + e]; }
    int pos = atomicAdd(&g_cursor[dst], 1);
    g_srclist[g_off[dst] + pos] = src;
}

// ---------------- aggregation fused with BOTH hi/lo conversions ----------------
// writes mean(neighbors) to A' cols [0:256)/[512:768), own x row to [256:512)/[768:1024)
#define AGG_TILE 64
__global__ void aggregate_kernel(const float* __restrict__ x) {
    int n = blockIdx.x;
    int c = threadIdx.x;
    __shared__ int ssrc[AGG_TILE];

    // fused conv_x: own row (L2-hot)
    {
        float v = x[(size_t)n * D + c];
        __nv_bfloat16 hi, lo;
        split_bf16(v, hi, lo);
        g_Ahl[(size_t)n * 1024 + 256 + c] = hi;
        g_Ahl[(size_t)n * 1024 + 768 + c] = lo;
    }

    int off0 = g_off[n];
    int off1 = g_off[n + 1];
    float sum = 0.f;
    for (int base = off0; base < off1; base += AGG_TILE) {
        int cnt = min(AGG_TILE, off1 - base);
        __syncthreads();
        if (c < cnt) ssrc[c] = g_srclist[base + c];
        __syncthreads();
#pragma unroll 4
        for (int i = 0; i < cnt; i++)
            sum += __ldg(&x[(size_t)ssrc[i] * D + c]);
    }
    float m = sum * (1.0f / fmaxf((float)(off1 - off0), 1.0f));
    __nv_bfloat16 hi, lo;
    split_bf16(m, hi, lo);
    g_Ahl[(size_t)n * 1024 + c] = hi;
    g_Ahl[(size_t)n * 1024 + 512 + c] = lo;
}

// ---------------- mma.sync bf16 GEMM ----------------
// out[20000,256] = A'[20000,1536_eff] @ W'^T + bias, via 24 K-chunks of 64.
// CTA tile 128x128, 8 warps (2M x 4N), warp tile 64x32, m16n8k16 HMMA.
// Smem tiles [128 rows][64 bf16] with 16B-chunk XOR swizzle (chunk ^ (row&7)).
#define GT 256
#define CHUNKS 24
#define SM_BIAS   0
#define SM_TILES  1024
#define SM_A(b)   (SM_TILES + (b) * 32768)
#define SM_B(b)   (SM_TILES + (b) * 32768 + 16384)
#define GEMM_SMEM (SM_TILES + 65536)

extern __shared__ char sm_dyn[];

__device__ __forceinline__ void stage_chunk(uint32_t sb, int b, int c, int row0, int col0,
                                            int tid) {
    int p  = c >> 3;
    int kc = (c & 7) * 64;
    int Acol = (p == 2) ? 512 : 0;
    int Wcol = (p == 1) ? 512 : 0;
    uint32_t smA = sb + SM_A(b), smB = sb + SM_B(b);
    const char* Abase = (const char*)g_Ahl;
    const char* Bbase = (const char*)g_Whl;
#pragma unroll
    for (int it = 0; it < 4; it++) {
        int u = it * GT + tid;              // 0..1023
        int r  = u >> 3;                    // row 0..127
        int ck = u & 7;                     // 16B chunk 0..7
        uint32_t swo = (uint32_t)(r * 8 + (ck ^ (r & 7))) * 16;
        int grow = row0 + r;
        int ok = (grow < N_NODES);
        const char* asrc = Abase + ((size_t)(ok ? grow : 0) * 1024 + Acol + kc + ck * 8) * 2;
        cp16(smA + swo, asrc, ok ? 16 : 0);
        const char* bsrc = Bbase + ((size_t)(col0 + r) * 1024 + Wcol + kc + ck * 8) * 2;
        cp16(smB + swo, bsrc, 16);
    }
    cp_commit();
}

__global__ void __launch_bounds__(GT, 2)
gemm_mma_kernel(const float* __restrict__ br, float* __restrict__ out) {
    uint32_t sb = smem_u32(sm_dyn);
    int tid  = threadIdx.x;
    int wid  = tid >> 5;
    int lane = tid & 31;
    int row0 = blockIdx.x * 128;
    int col0 = blockIdx.y * 128;
    int m0w  = (wid & 1) * 64;
    int n0w  = (wid >> 1) * 32;

    float* sBias = (float*)(sm_dyn + SM_BIAS);
    if (tid < 256) sBias[tid] = br[tid];

    float acc[4][4][4];
#pragma unroll
    for (int mt = 0; mt < 4; mt++)
#pragma unroll
        for (int nt = 0; nt < 4; nt++)
#pragma unroll
            for (int j = 0; j < 4; j++) acc[mt][nt][j] = 0.f;

    int a_m  = m0w + (lane & 15);
    int a_kh = (lane >> 4);
    int b_n  = n0w + (lane & 7) + ((lane >> 4) & 1) * 8;
    int b_kh = (lane >> 3) & 1;

    stage_chunk(sb, 0, 0, row0, col0, tid);

    for (int c = 0; c < CHUNKS; c++) {
        int b = c & 1;
        if (c + 1 < CHUNKS) {
            stage_chunk(sb, b ^ 1, c + 1, row0, col0, tid);
            cp_wait1();
        } else {
            cp_wait0();
        }
        __syncthreads();

        uint32_t smA = sb + SM_A(b), smB = sb + SM_B(b);
#pragma unroll
        for (int ks = 0; ks < 4; ks++) {
            uint32_t afrag[4][4], bfrag[4][4];
            int ka = ks * 2 + a_kh;
            int kb = ks * 2 + b_kh;
#pragma unroll
            for (int mt = 0; mt < 4; mt++) {
                int m = a_m + mt * 16;
                ldm_x4(afrag[mt], smA + (uint32_t)(m * 8 + (ka ^ (m & 7))) * 16);
            }
#pragma unroll
            for (int np = 0; np < 2; np++) {
                int n = b_n + np * 16;
                uint32_t r4[4];
                ldm_x4(r4, smB + (uint32_t)(n * 8 + (kb ^ (n & 7))) * 16);
                bfrag[np * 2][0]     = r4[0]; bfrag[np * 2][1]     = r4[1];
                bfrag[np * 2 + 1][0] = r4[2]; bfrag[np * 2 + 1][1] = r4[3];
            }
#pragma unroll
            for (int mt = 0; mt < 4; mt++)
#pragma unroll
                for (int nt = 0; nt < 4; nt++)
                    mma16816(acc[mt][nt], afrag[mt], bfrag[nt]);
        }
        __syncthreads();
    }

    int cr = lane >> 2;
    int cc = (lane & 3) * 2;
#pragma unroll
    for (int mt = 0; mt < 4; mt++) {
        int r0g = row0 + m0w + mt * 16 + cr;
#pragma unroll
        for (int nt = 0; nt < 4; nt++) {
            int colg = col0 + n0w + nt * 8 + cc;
            float b0 = sBias[colg], b1 = sBias[colg + 1];
            if (r0g < N_NODES)
                *reinterpret_cast<float2*>(&out[(size_t)r0g * 256 + colg]) =
                    make_float2(acc[mt][nt][0] + b0, acc[mt][nt][1] + b1);
            if (r0g + 8 < N_NODES)
                *reinterpret_cast<float2*>(&out[(size_t)(r0g + 8) * 256 + colg]) =
                    make_float2(acc[mt][nt][2] + b0, acc[mt][nt][3] + b1);
        }
    }
}

// ---------------- launch ----------------
extern "C" void kernel_launch(void* const* d_in, const int* in_sizes, int n_in,
                              void* d_out, int out_size) {
    const float* x  = (const float*)d_in[0];
    const int*   ei = (const int*)d_in[1];
    const float* Wl = (const float*)d_in[2];
    const float* Wr = (const float*)d_in[3];
    const float* br = (const float*)d_in[4];
    float* out = (float*)d_out;

    cudaFuncSetAttribute(gemm_mma_kernel,
                         cudaFuncAttributeMaxDynamicSharedMemorySize, GEMM_SMEM);

    init_kernel<<<NB, 256>>>(ei);
    count_kernel<<<(N_EDGES + 255) / 256, 256>>>(ei, Wl, Wr);
    partsum_kernel<<<NB, 256>>>();
    scanwrite_kernel<<<NB, 256>>>();
    fill_kernel<<<(N_EDGES + 255) / 256, 256>>>(ei);
    aggregate_kernel<<<N_NODES, 256>>>(x);
    gemm_mma_kernel<<<dim3((N_NODES + 127) / 128, 2), GT, GEMM_SMEM>>>(br, out);
}